// round 1
// baseline (speedup 1.0000x reference)
#include <cuda_runtime.h>
#include <cub/cub.cuh>
#include <cstdint>

// Problem constants (fixed by the reference)
#define NN      2048
#define DF      512
#define MSUP    512
#define WORDS   32            // uint64 words per bitmask row (2048 bits)
#define NPAIRS  2096128       // N*(N-1)/2
#define TARGET  1536          // N - NUM_SUPER merges

// Output layout: X_coarse [512,512] | A_coarse [512,512] | P [2048,512]
#define XC_OFF  0
#define AC_OFF  262144
#define P_OFF   524288
#define OUT_N   1572864

// -------- scratch (device globals; no allocation allowed) --------
__device__ unsigned long long g_masks[NN * WORDS];     // 512 KB
__device__ int                g_deg[NN];
__device__ unsigned long long g_keys_in[NPAIRS];       // 16 MB
__device__ unsigned long long g_keys_out[NPAIRS];      // 16 MB
__device__ unsigned char      g_sort_temp[64u << 20];  // CUB temp
__device__ int                g_labels[NN];
__device__ float              g_wnode[NN];

// -------- 1) pack adjacency rows into bitmasks + degrees --------
__global__ void k_pack(const float* __restrict__ A) {
    int warp = (blockIdx.x * blockDim.x + threadIdx.x) >> 5;
    int lane = threadIdx.x & 31;
    if (warp >= NN) return;
    const float* row = A + (size_t)warp * NN;
    unsigned int* m32 = reinterpret_cast<unsigned int*>(g_masks) + (size_t)warp * (WORDS * 2);
    int deg = 0;
    #pragma unroll 4
    for (int k = 0; k < NN / 32; k++) {
        unsigned b = __ballot_sync(0xFFFFFFFFu, row[k * 32 + lane] > 0.0f);
        if (lane == 0) { m32[k] = b; deg += __popc(b); }
    }
    if (lane == 0) g_deg[warp] = deg;
}

// -------- 2) Jaccard + sort-key generation, 64x64 tiles --------
__global__ void k_keys() {
    int bi = blockIdx.y, bj = blockIdx.x;
    if (bj < bi) return;   // tile entirely below diagonal
    __shared__ unsigned long long sI[64 * WORDS];
    __shared__ unsigned long long sJ[64 * WORDS];
    __shared__ int dI[64], dJ[64];
    int tid = threadIdx.x;

    for (int t = tid; t < 64 * WORDS; t += 256) {
        sI[t] = g_masks[(size_t)(bi * 64) * WORDS + t];
        sJ[t] = g_masks[(size_t)(bj * 64) * WORDS + t];
    }
    for (int t = tid; t < 64; t += 256) {
        dI[t] = g_deg[bi * 64 + t];
        dJ[t] = g_deg[bj * 64 + t];
    }
    __syncthreads();

    for (int p = tid; p < 4096; p += 256) {
        int ti = p >> 6, tj = p & 63;
        int gi = bi * 64 + ti, gj = bj * 64 + tj;
        if (gi >= gj) continue;
        int inter = 0;
        #pragma unroll
        for (int w = 0; w < WORDS; w++)
            inter += __popcll(sI[ti * WORDS + w] & sJ[tj * WORDS + w]);
        int uni = dI[ti] + dJ[tj] - inter;
        // bit-exact match of reference: f32 division, correctly rounded.
        float jac = (uni == 0) ? 0.0f : __fdiv_rn((float)inter, (float)uni);
        unsigned fb = __float_as_uint(jac);   // jac >= +0 => bits monotone in value
        unsigned long long key =
            ((unsigned long long)(~fb) << 22) | (unsigned)(gi * NN + gj);
        long base = (long)gi * (2 * NN - gi - 1) / 2;   // triu linear index
        g_keys_in[base + (gj - gi - 1)] = key;
    }
}

// -------- 3) single-block union-find over sorted pairs --------
__device__ __forceinline__ int uf_find(int* p, int x) {
    while (p[x] != x) { p[x] = p[p[x]]; x = p[x]; }   // path halving (partition-equivalent)
    return x;
}

__global__ void k_uf() {
    __shared__ int parent[NN];
    __shared__ int lor[NN];           // label-of-root
    __shared__ int ssizes[MSUP];
    __shared__ float swc[MSUP];
    __shared__ unsigned long long chunk[2048];
    __shared__ int s_done;
    int tid = threadIdx.x;

    for (int t = tid; t < NN; t += blockDim.x) { parent[t] = t; lor[t] = -1; }
    for (int t = tid; t < MSUP; t += blockDim.x) ssizes[t] = 0;
    if (tid == 0) s_done = 0;
    __syncthreads();

    int merged = 0;                   // thread 0 only
    for (int base = 0; base < NPAIRS; base += 2048) {
        int cnt = min(2048, NPAIRS - base);
        for (int t = tid; t < cnt; t += blockDim.x) chunk[t] = g_keys_out[base + t];
        __syncthreads();
        if (tid == 0) {
            for (int k = 0; k < cnt; k++) {
                unsigned idx = (unsigned)(chunk[k] & 0x3FFFFFu);
                int i = idx >> 11, j = idx & 2047;
                int ri = uf_find(parent, i);
                int rj = uf_find(parent, j);
                if (ri != rj) {
                    parent[rj] = ri;
                    if (++merged == TARGET) { s_done = 1; break; }
                }
            }
        }
        __syncthreads();
        if (s_done) break;
    }

    // labeling: rank of component's minimum node index (first occurrence scan)
    if (tid == 0) {
        int next = 0;
        for (int i = 0; i < NN; i++) {
            int r = uf_find(parent, i);
            int l = lor[r];
            if (l < 0) { l = next++; lor[r] = l; }
            g_labels[i] = l;
            ssizes[l]++;
        }
    }
    __syncthreads();
    for (int t = tid; t < MSUP; t += blockDim.x)
        swc[t] = 1.0f / sqrtf((float)ssizes[t] + 1e-10f);
    __syncthreads();
    for (int t = tid; t < NN; t += blockDim.x)
        g_wnode[t] = swc[g_labels[t]];
}

// -------- 4) epilogue --------
__global__ void k_zero(float* out) {
    int t = blockIdx.x * blockDim.x + threadIdx.x;
    float4 z = make_float4(0.f, 0.f, 0.f, 0.f);
    for (int i = t; i < OUT_N / 4; i += gridDim.x * blockDim.x)
        reinterpret_cast<float4*>(out)[i] = z;
}

__global__ void k_fill_P(float* out) {
    int i = blockIdx.x * blockDim.x + threadIdx.x;
    if (i < NN) out[P_OFF + i * MSUP + g_labels[i]] = g_wnode[i];
}

__global__ void k_xcoarse(const float* __restrict__ X, float* out) {
    int t = blockIdx.x * blockDim.x + threadIdx.x;
    if (t < NN * DF) {
        int i = t >> 9, d = t & (DF - 1);
        atomicAdd(&out[XC_OFF + g_labels[i] * DF + d], g_wnode[i] * X[t]);
    }
}

__global__ void k_acoarse(const float* __restrict__ A, float* out) {
    int t = blockIdx.x * blockDim.x + threadIdx.x;
    if (t < NN * NN) {
        float a = A[t];
        if (a != 0.0f) {
            int i = t >> 11, j = t & (NN - 1);
            atomicAdd(&out[AC_OFF + g_labels[i] * MSUP + g_labels[j]],
                      g_wnode[i] * g_wnode[j] * a);
        }
    }
}

// -------- launch --------
extern "C" void kernel_launch(void* const* d_in, const int* in_sizes, int n_in,
                              void* d_out, int out_size) {
    const float* X = (const float*)d_in[0];
    const float* A = (const float*)d_in[1];
    float* out = (float*)d_out;

    k_pack<<<NN / 8, 256>>>(A);

    dim3 g2(32, 32);
    k_keys<<<g2, 256>>>();

    void *d_kin, *d_kout, *d_tmp;
    cudaGetSymbolAddress(&d_kin, g_keys_in);
    cudaGetSymbolAddress(&d_kout, g_keys_out);
    cudaGetSymbolAddress(&d_tmp, g_sort_temp);
    size_t tmp_bytes = 0;
    cub::DeviceRadixSort::SortKeys(nullptr, tmp_bytes,
        (const unsigned long long*)d_kin, (unsigned long long*)d_kout,
        NPAIRS, 0, 54);
    // keys occupy bits [0,54): 32-bit negated sim in [22,54), pair idx in [0,22)
    cub::DeviceRadixSort::SortKeys(d_tmp, tmp_bytes,
        (const unsigned long long*)d_kin, (unsigned long long*)d_kout,
        NPAIRS, 0, 54);

    k_uf<<<1, 1024>>>();

    k_zero<<<256, 256>>>(out);
    k_fill_P<<<NN / 256, 256>>>(out);
    k_xcoarse<<<(NN * DF) / 256, 256>>>(X, out);
    k_acoarse<<<(NN * NN) / 256, 256>>>(A, out);
}

// round 2
// speedup vs baseline: 1.3246x; 1.3246x over previous
#include <cuda_runtime.h>
#include <cub/cub.cuh>
#include <cstdint>

// Problem constants (fixed by the reference)
#define NN      2048
#define DF      512
#define MSUP    512
#define NPAIRS  2096128       // N*(N-1)/2  (== 2047 * 1024 exactly)
#define TARGET  1536          // N - NUM_SUPER merges
#define MAXDEG  512           // adjacency-list capacity per node (avg deg ~20)

// Output layout: X_coarse [512,512] | A_coarse [512,512] | P [2048,512]
#define XC_OFF  0
#define AC_OFF  262144
#define P_OFF   524288
#define OUT_N   1572864

// -------- scratch (device globals; no allocation allowed) --------
__device__ int           g_adj[NN * MAXDEG];      // 4 MB
__device__ int           g_deg[NN];
__device__ int           g_inter[NN * NN];        // 16 MB (upper triangle used)
__device__ unsigned      g_keys_in[NPAIRS];       // 8 MB
__device__ unsigned      g_keys_out[NPAIRS];      // 8 MB
__device__ unsigned      g_vals_in[NPAIRS];       // 8 MB (pair index payload)
__device__ unsigned      g_vals_out[NPAIRS];      // 8 MB
__device__ unsigned char g_sort_temp[64u << 20];  // CUB temp
__device__ int           g_labels[NN];
__device__ float         g_wnode[NN];

// -------- 1) adjacency lists + degrees (warp per row, ascending j) --------
__global__ void k_adj(const float* __restrict__ A) {
    int warp = (blockIdx.x * blockDim.x + threadIdx.x) >> 5;
    int lane = threadIdx.x & 31;
    if (warp >= NN) return;
    const float* row = A + (size_t)warp * NN;
    int cnt = 0;
    for (int k = 0; k < NN; k += 32) {
        float v = row[k + lane];
        unsigned b = __ballot_sync(0xFFFFFFFFu, v > 0.0f);
        if (v > 0.0f) {
            int pos = cnt + __popc(b & ((1u << lane) - 1u));
            if (pos < MAXDEG) g_adj[warp * MAXDEG + pos] = k + lane;
        }
        cnt += __popc(b);
    }
    if (lane == 0) g_deg[warp] = cnt;
}

// -------- 2) zero the intersection-count matrix --------
__global__ void k_zero_inter() {
    size_t t = (size_t)blockIdx.x * blockDim.x + threadIdx.x;
    int4 z = make_int4(0, 0, 0, 0);
    for (size_t i = t; i < (size_t)NN * NN / 4; i += (size_t)gridDim.x * blockDim.x)
        reinterpret_cast<int4*>(g_inter)[i] = z;
}

// -------- 3) sparse triangle counting: inter[i][j] += 1 per common neighbor --------
// Total work = sum_k deg(k)^2/2 ~ 400k atomics (vs 4.3G dense bit-ops).
__global__ void k_tri() {
    int warp = (blockIdx.x * blockDim.x + threadIdx.x) >> 5;
    int lane = threadIdx.x & 31;
    if (warp >= NN) return;
    int d = min(g_deg[warp], MAXDEG);
    const int* nb = &g_adj[warp * MAXDEG];
    for (int a = 0; a < d - 1; a++) {
        int i = nb[a];                        // ascending list => i < j below
        int* irow = &g_inter[i * NN];
        for (int b = a + 1 + lane; b < d; b += 32)
            atomicAdd(&irow[nb[b]], 1);
    }
}

// -------- 4) sort keys: 32-bit negated float bits; payload = pair index --------
__global__ void k_keygen() {
    __shared__ int sdeg[NN];
    int i = blockIdx.x;
    for (int t = threadIdx.x; t < NN; t += blockDim.x) sdeg[t] = g_deg[t];
    __syncthreads();
    if (i >= NN - 1) return;
    int di = sdeg[i];
    long base = (long)i * (2 * NN - i - 1) / 2;   // triu linear offset of row i
    const int* irow = &g_inter[i * NN];
    for (int j = i + 1 + threadIdx.x; j < NN; j += blockDim.x) {
        int inter = irow[j];
        int uni = di + sdeg[j] - inter;
        // bit-exact vs reference: f32 correctly-rounded division; union==0 path
        // yields 0/EPS == +0.0f identically.
        float jac = (uni == 0) ? 0.0f : __fdiv_rn((float)inter, (float)uni);
        unsigned fb = __float_as_uint(jac);       // jac >= +0 => bits monotone
        long o = base + (j - i - 1);
        g_keys_in[o] = ~fb;                       // ascending ~fb == descending jac
        g_vals_in[o] = (unsigned)(i * NN + j);    // stable sort => index tie-break
    }
}

// -------- 5) union-find: parallel reject pre-filter + serial candidate pass --------
__global__ void k_uf() {
    __shared__ int parent[NN];
    __shared__ int lor[NN];
    __shared__ int ssz[MSUP];
    __shared__ float swc[MSUP];
    __shared__ unsigned s_idx[1024];
    __shared__ int s_cnt[32], s_off[33];
    __shared__ int s_done;
    int tid = threadIdx.x, lane = tid & 31, w = tid >> 5;

    for (int t = tid; t < NN; t += 1024) { parent[t] = t; lor[t] = -1; }
    for (int t = tid; t < MSUP; t += 1024) ssz[t] = 0;
    if (tid == 0) s_done = 0;
    __syncthreads();

    int merged = 0;                      // thread 0 only
    for (int base = 0; base < NPAIRS; base += 1024) {   // NPAIRS % 1024 == 0
        // parallel phase: read-only find (parent static here). Union only merges
        // components, so "roots already equal" is a FINAL reject.
        unsigned idx = g_vals_out[base + tid];
        int i = idx >> 11, j = idx & (NN - 1);
        int ri = i; while (parent[ri] != ri) ri = parent[ri];
        int rj = j; while (parent[rj] != rj) rj = parent[rj];
        bool cand = (ri != rj);

        unsigned b = __ballot_sync(0xFFFFFFFFu, cand);
        if (lane == 0) s_cnt[w] = __popc(b);
        __syncthreads();
        if (tid == 0) {
            int acc = 0;
            #pragma unroll
            for (int k = 0; k < 32; k++) { s_off[k] = acc; acc += s_cnt[k]; }
            s_off[32] = acc;
        }
        __syncthreads();
        if (cand) s_idx[s_off[w] + __popc(b & ((1u << lane) - 1u))] = idx;
        __syncthreads();

        if (tid == 0) {
            int nc = s_off[32];
            for (int c = 0; c < nc; c++) {
                unsigned id = s_idx[c];
                int a = id >> 11, bb = id & (NN - 1);
                int ra = a;  while (parent[ra] != ra) { parent[ra] = parent[parent[ra]]; ra = parent[ra]; }
                int rb = bb; while (parent[rb] != rb) { parent[rb] = parent[parent[rb]]; rb = parent[rb]; }
                if (ra != rb) {
                    parent[rb] = ra;
                    if (++merged == TARGET) { s_done = 1; break; }
                }
            }
        }
        __syncthreads();
        if (s_done) break;
    }

    // labeling: rank of component's minimum node index (first-occurrence scan)
    if (tid == 0) {
        int next = 0;
        for (int i = 0; i < NN; i++) {
            int r = i; while (parent[r] != r) { parent[r] = parent[parent[r]]; r = parent[r]; }
            int l = lor[r];
            if (l < 0) { l = next++; lor[r] = l; }
            g_labels[i] = l;
            ssz[l]++;
        }
    }
    __syncthreads();
    for (int t = tid; t < MSUP; t += 1024)
        swc[t] = 1.0f / sqrtf((float)ssz[t] + 1e-10f);
    __syncthreads();
    for (int t = tid; t < NN; t += 1024)
        g_wnode[t] = swc[g_labels[t]];
}

// -------- 6) epilogue --------
__global__ void k_zero(float* out) {
    int t = blockIdx.x * blockDim.x + threadIdx.x;
    float4 z = make_float4(0.f, 0.f, 0.f, 0.f);
    for (int i = t; i < OUT_N / 4; i += gridDim.x * blockDim.x)
        reinterpret_cast<float4*>(out)[i] = z;
}

__global__ void k_fill_P(float* out) {
    int i = blockIdx.x * blockDim.x + threadIdx.x;
    if (i < NN) out[P_OFF + i * MSUP + g_labels[i]] = g_wnode[i];
}

__global__ void k_xcoarse(const float* __restrict__ X, float* out) {
    int t = blockIdx.x * blockDim.x + threadIdx.x;
    if (t < NN * DF) {
        int i = t >> 9, d = t & (DF - 1);
        atomicAdd(&out[XC_OFF + g_labels[i] * DF + d], g_wnode[i] * X[t]);
    }
}

// A_coarse over adjacency lists: ~41k edges instead of 4M-element scan.
__global__ void k_acoarse(const float* __restrict__ A, float* out) {
    int warp = (blockIdx.x * blockDim.x + threadIdx.x) >> 5;
    int lane = threadIdx.x & 31;
    if (warp >= NN) return;
    int i = warp;
    int d = min(g_deg[i], MAXDEG);
    float wi = g_wnode[i];
    int li = g_labels[i];
    for (int a = lane; a < d; a += 32) {
        int j = g_adj[i * MAXDEG + a];
        float v = A[(size_t)i * NN + j];
        atomicAdd(&out[AC_OFF + li * MSUP + g_labels[j]], wi * g_wnode[j] * v);
    }
}

// -------- launch --------
extern "C" void kernel_launch(void* const* d_in, const int* in_sizes, int n_in,
                              void* d_out, int out_size) {
    const float* X = (const float*)d_in[0];
    const float* A = (const float*)d_in[1];
    float* out = (float*)d_out;

    k_adj<<<NN / 8, 256>>>(A);
    k_zero_inter<<<256, 256>>>();
    k_tri<<<NN / 8, 256>>>();
    k_keygen<<<NN, 256>>>();

    void *d_kin, *d_kout, *d_vin, *d_vout, *d_tmp;
    cudaGetSymbolAddress(&d_kin, g_keys_in);
    cudaGetSymbolAddress(&d_kout, g_keys_out);
    cudaGetSymbolAddress(&d_vin, g_vals_in);
    cudaGetSymbolAddress(&d_vout, g_vals_out);
    cudaGetSymbolAddress(&d_tmp, g_sort_temp);
    size_t tmp_bytes = 0;
    cub::DeviceRadixSort::SortPairs(nullptr, tmp_bytes,
        (const unsigned*)d_kin, (unsigned*)d_kout,
        (const unsigned*)d_vin, (unsigned*)d_vout,
        NPAIRS, 0, 32);
    cub::DeviceRadixSort::SortPairs(d_tmp, tmp_bytes,
        (const unsigned*)d_kin, (unsigned*)d_kout,
        (const unsigned*)d_vin, (unsigned*)d_vout,
        NPAIRS, 0, 32);

    k_uf<<<1, 1024>>>();

    k_zero<<<256, 256>>>(out);
    k_fill_P<<<NN / 256, 256>>>(out);
    k_xcoarse<<<(NN * DF) / 256, 256>>>(X, out);
    k_acoarse<<<NN / 8, 256>>>(A, out);
}